// round 11
// baseline (speedup 1.0000x reference)
#include <cuda_runtime.h>
#include <cstdint>

// out[b, c*12+i, h, w] = sum_{k,j} w1[i,k,j] * y[(h+k-4), (w-1)%112, j]
//   y[m, w', j] = sum_{j0} x[b, c*12+j0, m%112, w'] * w2[j0, j]
//   row m valid iff -1 <= m <= 110 (m == -1 wraps to x row 111), else zeros
// y stored UNSHIFTED in SMEM (stage-1 LDG/STS fully aligned+coalesced);
// +1 w-roll applied at the stage-2 global store (2x STG.32).
// Stage 2: thread = (col-pair, channel-quarter, 8-row block):
//   3 channels x 2 cols x 8 rows, rolling 9-row y window.
// 448 threads, TILE_H=16, 2 CTAs/SM. All math packed fp32x2.

#define HH 112
#define WW 112
#define TILE_H 16
#define YROWS 22          // TILE_H + 6 halo
#define NJ 12
#define NI 9
#define NO 12
#define THREADS 448

typedef unsigned long long u64;

__device__ __forceinline__ u64 fma2(u64 a, u64 b, u64 c) {
    u64 d;
    asm("fma.rn.f32x2 %0, %1, %2, %3;" : "=l"(d) : "l"(a), "l"(b), "l"(c));
    return d;
}
__device__ __forceinline__ u64 pack2(float lo, float hi) {
    u64 d;
    asm("mov.b64 %0, {%1, %2};" : "=l"(d) : "f"(lo), "f"(hi));
    return d;
}
__device__ __forceinline__ void unpack2(u64 v, float& lo, float& hi) {
    asm("mov.b64 {%0, %1}, %2;" : "=f"(lo), "=f"(hi) : "l"(v));
}

// dynamic smem:
//   u64  w1q[4*63*4] : w1 per-quarter blocks [q][j*7+k][t(3 used, pad 4)]
//                      (dup-lane f32x2), 32B stride per (j,k) -> aligned LDS.128
//   u64  w2d[144]    : w2 [j0][i] padded to 12/row (dup f32x2)
//   float ysm[YROWS][NI][WW]  (22*9*112*4 = 88704 B), UNSHIFTED columns
#define SMEM_W1Q_ELEMS (4 * 63 * 4)
#define SMEM_W2D_ELEMS 144
#define SMEM_Y_OFF ((SMEM_W1Q_ELEMS + SMEM_W2D_ELEMS) * 8)
#define SMEM_TOTAL (SMEM_Y_OFF + YROWS * NI * WW * 4)

__global__ void __launch_bounds__(THREADS, 2)
fused_shiftconv_kernel(const float* __restrict__ x,
                       const float* __restrict__ w1,
                       const float* __restrict__ w2,
                       float* __restrict__ out)
{
    extern __shared__ char smem[];
    u64* w1q = reinterpret_cast<u64*>(smem);
    u64* w2d = w1q + SMEM_W1Q_ELEMS;
    float* ysm = reinterpret_cast<float*>(smem + SMEM_Y_OFF);

    const int tid = threadIdx.x;
    const int h0  = blockIdx.x * TILE_H;   // 7 tiles
    const int c   = blockIdx.y;            // 2 groups
    const int b   = blockIdx.z;            // 128 batches

    // ---- weight repack (duplicated f32x2) ----
    // src w1 layout [i][k][j]: idx = i*63 + k*9 + j
    for (int idx = tid; idx < 756; idx += THREADS) {
        int i = idx / 63;
        int rem = idx - i * 63;
        int k = rem / 9;
        int j = rem - k * 9;
        float v = w1[idx];
        int q = i / 3;
        int t = i - q * 3;
        w1q[((q * 63) + (j * 7 + k)) * 4 + t] = pack2(v, v);
    }
    for (int idx = tid; idx < 108; idx += THREADS) {
        int j0 = idx / 9;
        int i  = idx - j0 * 9;
        float v = w2[idx];
        w2d[j0 * 12 + i] = pack2(v, v);
    }
    __syncthreads();

    const float* xb = x + (size_t)(b * 24 + c * 12) * (HH * WW);

    // ---- stage 1: y[l][i][w'] = sum_j0 x[j0, (h0+l-4)%112, w'] * w2[j0][i]
    // item = (l, wq): aligned LDG.128 of x cols 4wq..4wq+3; aligned STS.128 out.
    for (int g = tid; g < YROWS * 28; g += THREADS) {
        int l  = g / 28;
        int wq = g - l * 28;
        int m  = h0 + l - 4;
        float* yrow = ysm + (size_t)(l * NI) * WW + (wq << 2);
        if (m >= -1 && m <= 110) {
            int xr = (m < 0) ? (m + HH) : m;   // only m == -1 wraps (row 111)
            const float4* xrow = reinterpret_cast<const float4*>(
                xb + (size_t)xr * WW + (wq << 2));
            u64 acc[2][NI];
            #pragma unroll
            for (int v = 0; v < 2; ++v)
                #pragma unroll
                for (int i = 0; i < NI; ++i) acc[v][i] = 0ULL;

            #pragma unroll 4
            for (int j0 = 0; j0 < NJ; ++j0) {
                float4 xv = __ldg(xrow + (size_t)j0 * (HH * WW / 4));
                u64 xq0 = pack2(xv.x, xv.y);
                u64 xq1 = pack2(xv.z, xv.w);
                const u64* wr = w2d + j0 * 12;
                #pragma unroll
                for (int i = 0; i < NI; ++i) {
                    u64 wv = wr[i];
                    acc[0][i] = fma2(xq0, wv, acc[0][i]);
                    acc[1][i] = fma2(xq1, wv, acc[1][i]);
                }
            }
            #pragma unroll
            for (int i = 0; i < NI; ++i) {
                ulonglong2 st;
                st.x = acc[0][i];
                st.y = acc[1][i];
                *reinterpret_cast<ulonglong2*>(yrow + i * WW) = st;
            }
        } else {
            ulonglong2 z; z.x = 0ULL; z.y = 0ULL;
            #pragma unroll
            for (int i = 0; i < NI; ++i)
                *reinterpret_cast<ulonglong2*>(yrow + i * WW) = z;
        }
    }
    __syncthreads();

    // ---- stage 2: 7-tap conv, 3 channels x 2 cols x 8 rows per thread ----
    // rolling y window: live rows k..k+8, prefetch row k+8 each iteration
    {
        const int u  = tid % 56;              // y col pair (2u, 2u+1)
        const int q  = (tid / 56) & 3;        // channels [3q, 3q+3)
        const int rb = tid / 224;             // 0..1 -> 8-row block
        const int hl = rb * 8;
        u64 acc[8][3];
        #pragma unroll
        for (int r = 0; r < 8; ++r)
            #pragma unroll
            for (int i = 0; i < 3; ++i) acc[r][i] = 0ULL;

        const float* ycol = ysm + 2 * u + (size_t)hl * NI * WW;
        const u64* wq = w1q + (size_t)q * 63 * 4;
        #pragma unroll 1
        for (int j = 0; j < NI; ++j) {
            const float* yj = ycol + (size_t)j * WW;
            u64 yw[15];                       // rows hl..hl+14 (<=9 live)
            #pragma unroll
            for (int t = 0; t < 8; ++t)
                yw[t] = *reinterpret_cast<const u64*>(yj + (size_t)t * NI * WW);
            const u64* wj = wq + (size_t)j * 7 * 4;
            #pragma unroll
            for (int k = 0; k < 7; ++k) {
                if (k < 6)                    // prefetch row k+8 for next iter
                    yw[k + 8] = *reinterpret_cast<const u64*>(
                        yj + (size_t)(k + 8) * NI * WW);
                ulonglong2 p01 =
                    *reinterpret_cast<const ulonglong2*>(wj + k * 4);
                u64 w2v = wj[k * 4 + 2];
                #pragma unroll
                for (int r = 0; r < 8; ++r) {
                    u64 yv = yw[r + k];
                    acc[r][0] = fma2(yv, p01.x, acc[r][0]);
                    acc[r][1] = fma2(yv, p01.y, acc[r][1]);
                    acc[r][2] = fma2(yv, w2v,  acc[r][2]);
                }
            }
        }

        // +1 w-roll at the output: y cols (2u,2u+1) -> out cols (2u+1,(2u+2)%112)
        const int colA = 2 * u + 1;
        const int colB = (2 * u + 2 == WW) ? 0 : 2 * u + 2;
        float* ob = out + ((size_t)(b * 24 + c * 12 + q * 3) * HH
                           + (h0 + hl)) * WW;
        #pragma unroll
        for (int i = 0; i < 3; ++i) {
            float* orow = ob + (size_t)i * (HH * WW);
            #pragma unroll
            for (int r = 0; r < 8; ++r) {
                float lo, hi;
                unpack2(acc[r][i], lo, hi);
                orow[r * WW + colA] = lo;
                orow[r * WW + colB] = hi;
            }
        }
    }
}

extern "C" void kernel_launch(void* const* d_in, const int* in_sizes, int n_in,
                              void* d_out, int out_size)
{
    (void)in_sizes; (void)n_in; (void)out_size;
    const float* x  = (const float*)d_in[0];
    const float* w1 = (const float*)d_in[1];
    const float* w2 = (const float*)d_in[2];
    float* out = (float*)d_out;

    cudaFuncSetAttribute(fused_shiftconv_kernel,
                         cudaFuncAttributeMaxDynamicSharedMemorySize, SMEM_TOTAL);
    dim3 grid(HH / TILE_H, 2, 128);   // (7 h-tiles, 2 groups, 128 batches)
    fused_shiftconv_kernel<<<grid, THREADS, SMEM_TOTAL>>>(x, w1, w2, out);
}

// round 12
// speedup vs baseline: 1.2167x; 1.2167x over previous
#include <cuda_runtime.h>
#include <cstdint>

// out[b, c*12+i, h, w] = sum_{k,j} w1[i,k,j] * y[(h+k-4), (w-1)%112, j]
//   y[m, w', j] = sum_{j0} x[b, c*12+j0, m%112, w'] * w2[j0, j]
//   row m valid iff -1 <= m <= 110 (m == -1 wraps to x row 111), else zeros
// y stored UNSHIFTED in SMEM (stage-1 LDG/STS fully aligned+coalesced);
// +1 w-roll applied at the stage-2 global store (2x STG.32).
// Stage 2: thread = (col-pair, channel-half, 4-row block): 6ch x 2col x 4row,
// rolling 4-row y window. 448 threads, TILE_H=16, 2 CTAs/SM, <=72 regs.
// Stage 1: j0 unrolled by 6 -> LDG batches of 6 (MLP 6). All math fp32x2.

#define HH 112
#define WW 112
#define TILE_H 16
#define YROWS 22          // TILE_H + 6 halo
#define NJ 12
#define NI 9
#define NO 12
#define THREADS 448

typedef unsigned long long u64;

__device__ __forceinline__ u64 fma2(u64 a, u64 b, u64 c) {
    u64 d;
    asm("fma.rn.f32x2 %0, %1, %2, %3;" : "=l"(d) : "l"(a), "l"(b), "l"(c));
    return d;
}
__device__ __forceinline__ u64 pack2(float lo, float hi) {
    u64 d;
    asm("mov.b64 %0, {%1, %2};" : "=l"(d) : "f"(lo), "f"(hi));
    return d;
}
__device__ __forceinline__ void unpack2(u64 v, float& lo, float& hi) {
    asm("mov.b64 {%0, %1}, %2;" : "=f"(lo), "=f"(hi) : "l"(v));
}

// dynamic smem:
//   u64  w1d[756] : w1 repacked [j][k][i] (dup f32x2), 16B aligned
//   u64  w2d[144] : w2 [j0][i] padded to 12/row (dup f32x2)
//   float ysm[YROWS][NI][WW]  (22*9*112*4 = 88704 B), UNSHIFTED columns
#define SMEM_W1D_ELEMS 756
#define SMEM_W2D_ELEMS 144
#define SMEM_Y_OFF ((SMEM_W1D_ELEMS + SMEM_W2D_ELEMS) * 8)
#define SMEM_TOTAL (SMEM_Y_OFF + YROWS * NI * WW * 4)

__global__ void __launch_bounds__(THREADS, 2)
fused_shiftconv_kernel(const float* __restrict__ x,
                       const float* __restrict__ w1,
                       const float* __restrict__ w2,
                       float* __restrict__ out)
{
    extern __shared__ char smem[];
    u64* w1d = reinterpret_cast<u64*>(smem);
    u64* w2d = w1d + SMEM_W1D_ELEMS;
    float* ysm = reinterpret_cast<float*>(smem + SMEM_Y_OFF);

    const int tid = threadIdx.x;
    const int h0  = blockIdx.x * TILE_H;   // 7 tiles
    const int c   = blockIdx.y;            // 2 groups
    const int b   = blockIdx.z;            // 128 batches

    // ---- weight repack (duplicated f32x2) ----
    for (int idx = tid; idx < SMEM_W1D_ELEMS; idx += THREADS) {
        // src w1 layout [i][k][j]: idx = i*63 + k*9 + j
        int i = idx / 63;
        int rem = idx - i * 63;
        int k = rem / 9;
        int j = rem - k * 9;
        float v = w1[idx];
        w1d[(j * 7 + k) * 12 + i] = pack2(v, v);   // dst [j][k][i]
    }
    for (int idx = tid; idx < 108; idx += THREADS) {
        int j0 = idx / 9;
        int i  = idx - j0 * 9;
        float v = w2[idx];
        w2d[j0 * 12 + i] = pack2(v, v);
    }
    __syncthreads();

    const float* xb = x + (size_t)(b * 24 + c * 12) * (HH * WW);

    // ---- stage 1: y[l][i][w'] = sum_j0 x[j0, (h0+l-4)%112, w'] * w2[j0][i]
    // item = (l, wq): aligned LDG.128 of x cols 4wq..4wq+3; aligned STS.128 out.
    // j0 unrolled by 6: two batches of 6 independent LDG.128 (MLP 6).
    for (int g = tid; g < YROWS * 28; g += THREADS) {
        int l  = g / 28;
        int wq = g - l * 28;
        int m  = h0 + l - 4;
        float* yrow = ysm + (size_t)(l * NI) * WW + (wq << 2);
        if (m >= -1 && m <= 110) {
            int xr = (m < 0) ? (m + HH) : m;   // only m == -1 wraps (row 111)
            const float4* xrow = reinterpret_cast<const float4*>(
                xb + (size_t)xr * WW + (wq << 2));
            u64 acc[2][NI];
            #pragma unroll
            for (int v = 0; v < 2; ++v)
                #pragma unroll
                for (int i = 0; i < NI; ++i) acc[v][i] = 0ULL;

            #pragma unroll
            for (int jb = 0; jb < 2; ++jb) {
                float4 xv[6];
                #pragma unroll
                for (int t = 0; t < 6; ++t)
                    xv[t] = __ldg(xrow + (size_t)(jb * 6 + t) * (HH * WW / 4));
                #pragma unroll
                for (int t = 0; t < 6; ++t) {
                    u64 xq0 = pack2(xv[t].x, xv[t].y);
                    u64 xq1 = pack2(xv[t].z, xv[t].w);
                    const u64* wr = w2d + (jb * 6 + t) * 12;
                    #pragma unroll
                    for (int i = 0; i < NI; ++i) {
                        u64 wv = wr[i];
                        acc[0][i] = fma2(xq0, wv, acc[0][i]);
                        acc[1][i] = fma2(xq1, wv, acc[1][i]);
                    }
                }
            }
            #pragma unroll
            for (int i = 0; i < NI; ++i) {
                ulonglong2 st;
                st.x = acc[0][i];
                st.y = acc[1][i];
                *reinterpret_cast<ulonglong2*>(yrow + i * WW) = st;
            }
        } else {
            ulonglong2 z; z.x = 0ULL; z.y = 0ULL;
            #pragma unroll
            for (int i = 0; i < NI; ++i)
                *reinterpret_cast<ulonglong2*>(yrow + i * WW) = z;
        }
    }
    __syncthreads();

    // ---- stage 2: 7-tap conv, 6 channels x 2 cols x 4 rows per thread ----
    // rolling 4-row y window (prefetch row k+4 one k-iteration ahead)
    {
        const int u    = tid % 56;            // y col pair (2u, 2u+1)
        const int half = (tid / 56) & 1;      // channels [6*half, 6*half+6)
        const int rb   = tid / 112;           // 0..3 -> 4-row block
        const int hl   = rb * 4;
        u64 acc[4][6];
        #pragma unroll
        for (int r = 0; r < 4; ++r)
            #pragma unroll
            for (int i = 0; i < 6; ++i) acc[r][i] = 0ULL;

        const float* ycol = ysm + 2 * u + (size_t)hl * NI * WW;
        const ulonglong2* wbase =
            reinterpret_cast<const ulonglong2*>(w1d) + half * 3;
        #pragma unroll 1
        for (int j = 0; j < NI; ++j) {
            const float* yj = ycol + (size_t)j * WW;
            u64 yw[10];                       // rows hl..hl+9 (rolling live set)
            #pragma unroll
            for (int t = 0; t < 4; ++t)
                yw[t] = *reinterpret_cast<const u64*>(yj + (size_t)t * NI * WW);
            const ulonglong2* wj = wbase + j * 42;
            #pragma unroll
            for (int k = 0; k < 7; ++k) {
                if (k < 6)                    // prefetch row k+4 for next iter
                    yw[k + 4] = *reinterpret_cast<const u64*>(
                        yj + (size_t)(k + 4) * NI * WW);
                const ulonglong2* wk = wj + k * 6;
                ulonglong2 p0 = wk[0];
                #pragma unroll
                for (int r = 0; r < 4; ++r) {
                    acc[r][0] = fma2(yw[r + k], p0.x, acc[r][0]);
                    acc[r][1] = fma2(yw[r + k], p0.y, acc[r][1]);
                }
                ulonglong2 p1 = wk[1];
                #pragma unroll
                for (int r = 0; r < 4; ++r) {
                    acc[r][2] = fma2(yw[r + k], p1.x, acc[r][2]);
                    acc[r][3] = fma2(yw[r + k], p1.y, acc[r][3]);
                }
                ulonglong2 p2 = wk[2];
                #pragma unroll
                for (int r = 0; r < 4; ++r) {
                    acc[r][4] = fma2(yw[r + k], p2.x, acc[r][4]);
                    acc[r][5] = fma2(yw[r + k], p2.y, acc[r][5]);
                }
            }
        }

        // +1 w-roll at the output: y cols (2u,2u+1) -> out cols (2u+1,(2u+2)%112)
        const int colA = 2 * u + 1;
        const int colB = (2 * u + 2 == WW) ? 0 : 2 * u + 2;
        float* ob = out + ((size_t)(b * 24 + c * 12 + half * 6) * HH
                           + (h0 + hl)) * WW;
        #pragma unroll
        for (int i = 0; i < 6; ++i) {
            float* orow = ob + (size_t)i * (HH * WW);
            #pragma unroll
            for (int r = 0; r < 4; ++r) {
                float lo, hi;
                unpack2(acc[r][i], lo, hi);
                orow[r * WW + colA] = lo;
                orow[r * WW + colB] = hi;
            }
        }
    }
}

extern "C" void kernel_launch(void* const* d_in, const int* in_sizes, int n_in,
                              void* d_out, int out_size)
{
    (void)in_sizes; (void)n_in; (void)out_size;
    const float* x  = (const float*)d_in[0];
    const float* w1 = (const float*)d_in[1];
    const float* w2 = (const float*)d_in[2];
    float* out = (float*)d_out;

    cudaFuncSetAttribute(fused_shiftconv_kernel,
                         cudaFuncAttributeMaxDynamicSharedMemorySize, SMEM_TOTAL);
    dim3 grid(HH / TILE_H, 2, 128);   // (7 h-tiles, 2 groups, 128 batches)
    fused_shiftconv_kernel<<<grid, THREADS, SMEM_TOTAL>>>(x, w1, w2, out);
}